// round 5
// baseline (speedup 1.0000x reference)
#include <cuda_runtime.h>
#include <cstddef>

// Problem constants
#define NX 64
#define NU 32
#define NY 32
#define NW 64
#define BB 256
#define TT 2048

// Fused weight table gW[160][160] (row-major):
//  rows   0..63  (z):  [ C2*t_inv | D21*t_inv | 0        ]
//  rows  64..127 (x):  [ Yinv^T A | Yinv^T B1 | Yinv^T B2]
//  rows 128..159 (y):  [ C1       | D11       | D12      ]
__device__ float gW[160 * 160];

// Per-thread packed weights: gWT[s][80], s in [0,320) (same for both batches).
//  s in [0,128)   : z row s>>1, half h=s&1, 12 chunks c=h+2i (48 floats)
//  s in [128,256) : x row 64+((s-128)>>1), half h, 20 chunks c=h+2i (80 floats)
//  s in [256,320) : y row 128+((s-256)>>1), half h, 20 chunks c=h+2i (80 floats)
__device__ float gWT[320 * 80];

// ---------------------------------------------------------------------------
// Setup (single launch): Gauss-Jordan inverse of Y (no in-loop normalization),
// fold Y_inv and t_inv into gW, then pack into per-thread layout gWT.
// ---------------------------------------------------------------------------
__global__ void __launch_bounds__(512, 1)
setup_kernel(const float* __restrict__ Y,
             const float* __restrict__ lambdas,
             const float* __restrict__ A,
             const float* __restrict__ B1,
             const float* __restrict__ B2,
             const float* __restrict__ C1,
             const float* __restrict__ D11,
             const float* __restrict__ D12,
             const float* __restrict__ C2,
             const float* __restrict__ D21)
{
    __shared__ float M[64][128];   // augmented [Y | I]
    const int tid = threadIdx.x;   // 512 threads

    for (int e = tid; e < 64 * 128; e += 512) {
        int i = e >> 7, j = e & 127;
        M[i][j] = (j < 64) ? Y[i * 64 + j] : ((j - 64 == i) ? 1.0f : 0.0f);
    }
    __syncthreads();

    // Jordan elimination WITHOUT normalizing row k (diag folded later).
    for (int k = 0; k < 64; k++) {
        float pinv = 1.0f / M[k][k];
        float f[16];
        #pragma unroll
        for (int s = 0; s < 16; s++) {
            int e = tid + 512 * s;
            f[s] = M[e >> 7][k] * pinv;
        }
        __syncthreads();            // all reads done before writes
        #pragma unroll
        for (int s = 0; s < 16; s++) {
            int e = tid + 512 * s;
            int i = e >> 7, c = e & 127;
            if (i != k) M[i][c] -= f[s] * M[k][c];   // row k only read
        }
        __syncthreads();
    }
    // Normalize right half by residual diagonal: Yinv[i][j] = M[i][64+j]/M[i][i]
    for (int e = tid; e < 64 * 64; e += 512) {
        int i = e >> 6, j = e & 63;
        M[i][64 + j] *= (1.0f / M[i][i]);
    }
    __syncthreads();

    // --- build gW ---
    // z rows
    for (int e = tid; e < 64 * 64; e += 512) {
        int j = e >> 6, k2 = e & 63;
        gW[j * 160 + k2] = C2[j * 64 + k2] / lambdas[j];
        gW[j * 160 + 96 + k2] = 0.0f;
    }
    for (int e = tid; e < 64 * 32; e += 512) {
        int j = e >> 5, m = e & 31;
        gW[j * 160 + 64 + m] = D21[j * 32 + m] / lambdas[j];
    }
    // x rows: Atil[j][k] = sum_i Yinv[i][j]*A[i][k]  (+B1til, B2til)
    for (int e = tid; e < 64 * 64; e += 512) {
        int j = e >> 6, k2 = e & 63;
        float sA = 0.0f, sB2 = 0.0f;
        #pragma unroll 8
        for (int i = 0; i < 64; i++) {
            float yi = M[i][64 + j];
            sA  += yi * A[i * 64 + k2];
            sB2 += yi * B2[i * 64 + k2];
        }
        gW[(64 + j) * 160 + k2]      = sA;
        gW[(64 + j) * 160 + 96 + k2] = sB2;
    }
    for (int e = tid; e < 64 * 32; e += 512) {
        int j = e >> 5, m = e & 31;
        float s = 0.0f;
        #pragma unroll 8
        for (int i = 0; i < 64; i++) s += M[i][64 + j] * B1[i * 32 + m];
        gW[(64 + j) * 160 + 64 + m] = s;
    }
    // y rows
    for (int e = tid; e < 32 * 64; e += 512) {
        int j = e >> 6, k2 = e & 63;
        gW[(128 + j) * 160 + k2]      = C1[j * 64 + k2];
        gW[(128 + j) * 160 + 96 + k2] = D12[j * 64 + k2];
    }
    for (int e = tid; e < 32 * 32; e += 512) {
        int j = e >> 5, m = e & 31;
        gW[(128 + j) * 160 + 64 + m] = D11[j * 32 + m];
    }
    __syncthreads();

    // --- pack into per-thread layout ---
    for (int s = tid; s < 320; s += 512) {
        int row, h, nch;
        if (s < 128)      { row = s >> 1;               h = s & 1;         nch = 12; }
        else if (s < 256) { row = 64 + ((s - 128) >> 1); h = (s - 128) & 1; nch = 20; }
        else              { row = 128 + ((s - 256) >> 1); h = (s - 256) & 1; nch = 20; }
        for (int i = 0; i < nch; i++) {
            int c = h + 2 * i;
            #pragma unroll
            for (int j = 0; j < 4; j++)
                gWT[s * 80 + 4 * i + j] = gW[row * 160 + 4 * c + j];
        }
    }
}

// ---------------------------------------------------------------------------
// Main recurrent kernel: 128 CTAs x 640 threads, 2 batch chains per CTA.
// Every row is split across 2 adjacent lanes by chunk parity; phase 1 is
// perfectly balanced (every thread: 12 chunks = 24 FFMA2). Halves combine
// via shfl_xor(1). v = [x(64)|u(32)|w(64)] in smem (broadcast reads).
// ---------------------------------------------------------------------------

__device__ __forceinline__ float2 u64_as_f2(unsigned long long x) {
    float2 r;
    asm("mov.b64 {%0, %1}, %2;" : "=f"(r.x), "=f"(r.y) : "l"(x));
    return r;
}

#define FFMA2(acc, w, vv) \
    asm("fma.rn.f32x2 %0, %1, %2, %0;" : "+l"(acc) : "l"(w), "l"(vv))

#define BARB(id) asm volatile("bar.sync %0, 320;" :: "r"(id) : "memory")

__global__ void __launch_bounds__(640, 1)
rnn_kernel(const float* __restrict__ xpred, float* __restrict__ out, int write_xfinal)
{
    __shared__ __align__(16) float sv[2 * 160];

    const int tid   = threadIdx.x;
    const int batch = (tid >= 320) ? 1 : 0;
    const int s     = tid - 320 * batch;
    float* v = sv + batch * 160;
    const int bg = blockIdx.x * 2 + batch;
    const float* uptr = xpred + (size_t)bg * TT * NU;
    float* yout = out + (size_t)bg * TT * NY;
    const int barid = batch + 1;

    const bool isZ = (s < 128);
    int r, h;
    if (s < 128)      { r = s >> 1;                h = s & 1; }
    else if (s < 256) { r = 64 + ((s - 128) >> 1); h = (s - 128) & 1; }
    else              { r = 128 + ((s - 256) >> 1); h = (s - 256) & 1; }

    // One-time weight load into registers (contiguous in gWT).
    unsigned long long wreg[40];
    {
        const unsigned long long* grow = (const unsigned long long*)(gWT + s * 80);
        #pragma unroll
        for (int i = 0; i < 24; i++) wreg[i] = grow[i];
        if (!isZ) {
            #pragma unroll
            for (int i = 24; i < 40; i++) wreg[i] = grow[i];
        } else {
            #pragma unroll
            for (int i = 24; i < 40; i++) wreg[i] = 0ull;
        }
    }

    // init: x0 = 0; u_0 into v; u_1 into prefetch reg
    if (s < 64) v[s] = 0.0f;
    float u_next = 0.0f;
    if (s < 32) {
        v[64 + s] = uptr[s];
        u_next = uptr[NU + s];
    }
    BARB(barid);

    const float* vh = v + 4 * h;   // this half's chunk base: chunk i at vh + 8*i

    for (int t = 0; t < TT; t++) {
        // --- Phase 1: 12 chunks of v[0:96] for EVERY thread ---
        unsigned long long a0 = 0ull, a1 = 0ull;
        #pragma unroll
        for (int i = 0; i < 12; i++) {
            ulonglong2 vv = *(const ulonglong2*)(vh + 8 * i);
            FFMA2(a0, wreg[2 * i],     vv.x);
            FFMA2(a1, wreg[2 * i + 1], vv.y);
        }
        if (isZ) {
            float2 p = u64_as_f2(a0), q = u64_as_f2(a1);
            float acc = (p.x + q.x) + (p.y + q.y);
            acc += __shfl_xor_sync(0xffffffffu, acc, 1);  // combine halves
            float w = tanhf(acc);
            if (h == 0) v[96 + r] = w;                    // publish w
        }
        BARB(barid);   // w visible

        if (!isZ) {
            // --- Phase 2: 8 chunks of v[96:160] (i=12..19 => c=h+2i) ---
            #pragma unroll
            for (int i = 12; i < 20; i++) {
                ulonglong2 vv = *(const ulonglong2*)(vh + 8 * i);
                FFMA2(a0, wreg[2 * i],     vv.x);
                FFMA2(a1, wreg[2 * i + 1], vv.y);
            }
            float2 p = u64_as_f2(a0), q = u64_as_f2(a1);
            float acc = (p.x + q.x) + (p.y + q.y);
            acc += __shfl_xor_sync(0xffffffffu, acc, 1);  // combine halves
            if (h == 0) {
                if (r < 128) v[r - 64] = acc;                 // publish x_next
                else         yout[t * NY + (r - 128)] = acc;  // stream y
            }
        } else if (s < 32) {
            v[64 + s] = u_next;                               // u_{t+1}
            if (t + 2 < TT) u_next = uptr[(t + 2) * NU + s];
        }
        BARB(barid);   // x_next/u visible
    }

    if (write_xfinal && s < 64) {
        out[(size_t)BB * TT * NY + (size_t)bg * NX + s] = v[s];
    }
}

// ---------------------------------------------------------------------------
extern "C" void kernel_launch(void* const* d_in, const int* in_sizes, int n_in,
                              void* d_out, int out_size)
{
    const float* xpred   = (const float*)d_in[0];
    const float* Y       = (const float*)d_in[1];
    const float* lambdas = (const float*)d_in[2];
    const float* A       = (const float*)d_in[3];
    const float* B1      = (const float*)d_in[4];
    const float* B2      = (const float*)d_in[5];
    const float* C1      = (const float*)d_in[6];
    const float* D11     = (const float*)d_in[7];
    const float* D12     = (const float*)d_in[8];
    const float* C2      = (const float*)d_in[9];
    const float* D21     = (const float*)d_in[10];

    (void)in_sizes; (void)n_in;

    setup_kernel<<<1, 512>>>(Y, lambdas, A, B1, B2, C1, D11, D12, C2, D21);

    int write_xfinal = (out_size >= BB * TT * NY + BB * NX) ? 1 : 0;
    rnn_kernel<<<BB / 2, 640>>>(xpred, (float*)d_out, write_xfinal);
}

// round 6
// speedup vs baseline: 1.0173x; 1.0173x over previous
#include <cuda_runtime.h>
#include <cstddef>

// Problem constants
#define NX 64
#define NU 32
#define NY 32
#define NW 64
#define BB 256
#define TT 2048

// Fused weight table gW[160][160] (row-major):
//  rows   0..63  (z):  [ C2*t_inv | D21*t_inv | 0        ]
//  rows  64..127 (x):  [ Yinv^T A | Yinv^T B1 | Yinv^T B2]
//  rows 128..159 (y):  [ C1       | D11       | D12      ]
__device__ float gW[160 * 160];

// Per-thread packed weights: gWT[s][80], s in [0,320).
//  s in [0,128)   : z row s>>1, half h=s&1, 12 chunks c=h+2i (48 floats)
//  s in [128,256) : x row 64+((s-128)>>1), half h, 20 chunks c=h+2i (80 floats)
//  s in [256,320) : y row 128+((s-256)>>1), half h, 20 chunks c=h+2i (80 floats)
__device__ float gWT[320 * 80];

// Trajectory scratch for the decoupled y-pass.
// gXseq[b][t][64], t in [0,TT] (slot 0 = x_0 = 0, slot TT = x_final)
// gWseq[b][t][64], t in [0,TT)
__device__ float gXseq[(size_t)BB * (TT + 1) * NX];
__device__ float gWseq[(size_t)BB * TT * NW];

// ---------------------------------------------------------------------------
// Setup: Gauss-Jordan inverse of Y, fold Y_inv and t_inv into gW, pack gWT.
// ---------------------------------------------------------------------------
__global__ void __launch_bounds__(512, 1)
setup_kernel(const float* __restrict__ Y,
             const float* __restrict__ lambdas,
             const float* __restrict__ A,
             const float* __restrict__ B1,
             const float* __restrict__ B2,
             const float* __restrict__ C1,
             const float* __restrict__ D11,
             const float* __restrict__ D12,
             const float* __restrict__ C2,
             const float* __restrict__ D21)
{
    __shared__ float M[64][128];   // augmented [Y | I]
    const int tid = threadIdx.x;   // 512 threads

    for (int e = tid; e < 64 * 128; e += 512) {
        int i = e >> 7, j = e & 127;
        M[i][j] = (j < 64) ? Y[i * 64 + j] : ((j - 64 == i) ? 1.0f : 0.0f);
    }
    __syncthreads();

    for (int k = 0; k < 64; k++) {
        float pinv = 1.0f / M[k][k];
        float f[16];
        #pragma unroll
        for (int s = 0; s < 16; s++) {
            int e = tid + 512 * s;
            f[s] = M[e >> 7][k] * pinv;
        }
        __syncthreads();
        #pragma unroll
        for (int s = 0; s < 16; s++) {
            int e = tid + 512 * s;
            int i = e >> 7, c = e & 127;
            if (i != k) M[i][c] -= f[s] * M[k][c];
        }
        __syncthreads();
    }
    for (int e = tid; e < 64 * 64; e += 512) {
        int i = e >> 6, j = e & 63;
        M[i][64 + j] *= (1.0f / M[i][i]);
    }
    __syncthreads();

    // z rows
    for (int e = tid; e < 64 * 64; e += 512) {
        int j = e >> 6, k2 = e & 63;
        gW[j * 160 + k2] = C2[j * 64 + k2] / lambdas[j];
        gW[j * 160 + 96 + k2] = 0.0f;
    }
    for (int e = tid; e < 64 * 32; e += 512) {
        int j = e >> 5, m = e & 31;
        gW[j * 160 + 64 + m] = D21[j * 32 + m] / lambdas[j];
    }
    // x rows
    for (int e = tid; e < 64 * 64; e += 512) {
        int j = e >> 6, k2 = e & 63;
        float sA = 0.0f, sB2 = 0.0f;
        #pragma unroll 8
        for (int i = 0; i < 64; i++) {
            float yi = M[i][64 + j];
            sA  += yi * A[i * 64 + k2];
            sB2 += yi * B2[i * 64 + k2];
        }
        gW[(64 + j) * 160 + k2]      = sA;
        gW[(64 + j) * 160 + 96 + k2] = sB2;
    }
    for (int e = tid; e < 64 * 32; e += 512) {
        int j = e >> 5, m = e & 31;
        float s = 0.0f;
        #pragma unroll 8
        for (int i = 0; i < 64; i++) s += M[i][64 + j] * B1[i * 32 + m];
        gW[(64 + j) * 160 + 64 + m] = s;
    }
    // y rows
    for (int e = tid; e < 32 * 64; e += 512) {
        int j = e >> 6, k2 = e & 63;
        gW[(128 + j) * 160 + k2]      = C1[j * 64 + k2];
        gW[(128 + j) * 160 + 96 + k2] = D12[j * 64 + k2];
    }
    for (int e = tid; e < 32 * 32; e += 512) {
        int j = e >> 5, m = e & 31;
        gW[(128 + j) * 160 + 64 + m] = D11[j * 32 + m];
    }
    __syncthreads();

    // pack per-thread layout
    for (int s = tid; s < 320; s += 512) {
        int row, h, nch;
        if (s < 128)      { row = s >> 1;                h = s & 1;         nch = 12; }
        else if (s < 256) { row = 64 + ((s - 128) >> 1); h = (s - 128) & 1; nch = 20; }
        else              { row = 128 + ((s - 256) >> 1); h = (s - 256) & 1; nch = 20; }
        for (int i = 0; i < nch; i++) {
            int c = h + 2 * i;
            #pragma unroll
            for (int j = 0; j < 4; j++)
                gWT[s * 80 + 4 * i + j] = gW[row * 160 + 4 * c + j];
        }
    }
}

// ---------------------------------------------------------------------------
// FFMA2 helpers
// ---------------------------------------------------------------------------
__device__ __forceinline__ float2 u64_as_f2(unsigned long long x) {
    float2 r;
    asm("mov.b64 {%0, %1}, %2;" : "=f"(r.x), "=f"(r.y) : "l"(x));
    return r;
}
#define FFMA2(acc, w, vv) \
    asm("fma.rn.f32x2 %0, %1, %2, %0;" : "+l"(acc) : "l"(w), "l"(vv))
#define BARB(id) asm volatile("bar.sync %0, 256;" :: "r"(id) : "memory")

// ---------------------------------------------------------------------------
// Sequential kernel: 128 CTAs x 512 threads, 2 batch chains per CTA.
// Per batch (256 threads): 128 z-halves + 128 x-halves. y is NOT computed
// here; x_t and w_t stream to global scratch for the parallel y-pass.
// ---------------------------------------------------------------------------
__global__ void __launch_bounds__(512, 1)
rnn_kernel(const float* __restrict__ xpred)
{
    __shared__ __align__(16) float sv[2 * 160];

    const int tid   = threadIdx.x;
    const int batch = tid >> 8;        // 0/1
    const int s     = tid & 255;
    float* v = sv + batch * 160;
    const int bg = blockIdx.x * 2 + batch;
    const float* uptr = xpred + (size_t)bg * TT * NU;
    float* xseq = gXseq + (size_t)bg * (TT + 1) * NX;
    float* wseq = gWseq + (size_t)bg * TT * NW;
    const int barid = batch + 1;

    const bool isZ = (s < 128);
    const int r = isZ ? (s >> 1) : ((s - 128) >> 1);   // z row / state index
    const int h = isZ ? (s & 1)  : ((s - 128) & 1);

    // One-time weight load (z: 48 floats, x: 80 floats; contiguous in gWT)
    const int gs = isZ ? s : s;   // gWT slot: z at s, x at s (128..255) — same
    unsigned long long wreg[40];
    {
        const unsigned long long* grow = (const unsigned long long*)(gWT + gs * 80);
        #pragma unroll
        for (int i = 0; i < 24; i++) wreg[i] = grow[i];
        if (!isZ) {
            #pragma unroll
            for (int i = 24; i < 40; i++) wreg[i] = grow[i];
        } else {
            #pragma unroll
            for (int i = 24; i < 40; i++) wreg[i] = 0ull;
        }
    }

    // init: x0 = 0 in smem and in gXseq slot 0; u_0 into v; u_1 prefetched
    if (s < 64) {
        v[s] = 0.0f;
        xseq[s] = 0.0f;
    }
    float u_next = 0.0f;
    if (s >= 64 && s < 96) {        // use z threads not doing the x0 zeroing
        v[s] = uptr[s - 64];
        u_next = uptr[NU + (s - 64)];
    }
    BARB(barid);

    const float* vh = v + 4 * h;    // chunk i of this half at vh + 8*i

    for (int t = 0; t < TT; t++) {
        // --- Phase 1: 12 chunks of v[0:96] (all threads) ---
        unsigned long long a0 = 0ull, a1 = 0ull;
        #pragma unroll
        for (int i = 0; i < 12; i++) {
            ulonglong2 vv = *(const ulonglong2*)(vh + 8 * i);
            FFMA2(a0, wreg[2 * i],     vv.x);
            FFMA2(a1, wreg[2 * i + 1], vv.y);
        }
        if (isZ) {
            float2 p = u64_as_f2(a0), q = u64_as_f2(a1);
            float acc = (p.x + q.x) + (p.y + q.y);
            acc += __shfl_xor_sync(0xffffffffu, acc, 1);
            float w = tanhf(acc);
            if (h == 0) {
                v[96 + r] = w;                 // publish w for phase 2
                wseq[(size_t)t * NW + r] = w;  // stream w for y-pass
            }
        }
        BARB(barid);   // w visible

        if (!isZ) {
            // --- Phase 2: 8 chunks of v[96:160] ---
            #pragma unroll
            for (int i = 12; i < 20; i++) {
                ulonglong2 vv = *(const ulonglong2*)(vh + 8 * i);
                FFMA2(a0, wreg[2 * i],     vv.x);
                FFMA2(a1, wreg[2 * i + 1], vv.y);
            }
            float2 p = u64_as_f2(a0), q = u64_as_f2(a1);
            float acc = (p.x + q.x) + (p.y + q.y);
            acc += __shfl_xor_sync(0xffffffffu, acc, 1);
            if (h == 0) {
                v[r] = acc;                               // publish x_{t+1}
                xseq[(size_t)(t + 1) * NX + r] = acc;     // stream x for y-pass
            }
        } else if (s >= 64 && s < 96) {
            v[s] = u_next;                                // u_{t+1}
            if (t + 2 < TT) u_next = uptr[(size_t)(t + 2) * NU + (s - 64)];
        }
        BARB(barid);   // x_next / u visible
    }
}

// ---------------------------------------------------------------------------
// y-pass: y[b,t,:] = Wy * [x_t | u_t | w_t].  Grid (BB, TT/32), 256 threads.
// Thread = (t-slot g in 0..3, output j in 0..31, half h); weights (half y-row,
// 80 floats) in registers from gWT rows 256..319; 8 rounds of 4 timesteps.
// Also emits x_final (out tail) from gXseq slot TT.
// ---------------------------------------------------------------------------
__global__ void __launch_bounds__(256, 2)
ypass_kernel(const float* __restrict__ xpred, float* __restrict__ out, int write_xfinal)
{
    __shared__ __align__(16) float sv2[4 * 160];

    const int b    = blockIdx.x;
    const int tile = blockIdx.y;       // 0..63
    const int tid  = threadIdx.x;
    const int g = tid >> 6;            // timestep slot in round (0..3)
    const int q = tid & 63;            // (j,h)
    const int j = q >> 1, h = q & 1;

    const float* xseq = gXseq + (size_t)b * (TT + 1) * NX;
    const float* wseq = gWseq + (size_t)b * TT * NW;
    const float* uptr = xpred + (size_t)b * TT * NU;
    float* yout = out + (size_t)b * TT * NY;

    // weights: y half-row (20 chunks, 80 floats)
    unsigned long long wreg[40];
    {
        const unsigned long long* grow = (const unsigned long long*)(gWT + (256 + q) * 80);
        #pragma unroll
        for (int i = 0; i < 40; i++) wreg[i] = grow[i];
    }

    for (int rnd = 0; rnd < 8; rnd++) {
        const int t0 = tile * 32 + rnd * 4;
        // cooperative staging: 4 timesteps x 160 floats
        for (int e = tid; e < 4 * 160; e += 256) {
            int tl = e / 160, k = e - tl * 160;
            int t = t0 + tl;
            float val;
            if (k < 64)       val = xseq[(size_t)t * NX + k];
            else if (k < 96)  val = uptr[(size_t)t * NU + (k - 64)];
            else              val = wseq[(size_t)t * NW + (k - 96)];
            sv2[tl * 160 + k] = val;
        }
        __syncthreads();

        const float* vh = sv2 + g * 160 + 4 * h;
        unsigned long long a0 = 0ull, a1 = 0ull;
        #pragma unroll
        for (int i = 0; i < 20; i++) {
            ulonglong2 vv = *(const ulonglong2*)(vh + 8 * i);
            FFMA2(a0, wreg[2 * i],     vv.x);
            FFMA2(a1, wreg[2 * i + 1], vv.y);
        }
        float2 p = u64_as_f2(a0), qq = u64_as_f2(a1);
        float acc = (p.x + qq.x) + (p.y + qq.y);
        acc += __shfl_xor_sync(0xffffffffu, acc, 1);
        if (h == 0) yout[(size_t)(t0 + g) * NY + j] = acc;
        __syncthreads();
    }

    if (write_xfinal && tile == 0 && tid < NX) {
        out[(size_t)BB * TT * NY + (size_t)b * NX + tid] =
            gXseq[(size_t)b * (TT + 1) * NX + (size_t)TT * NX + tid];
    }
}

// ---------------------------------------------------------------------------
extern "C" void kernel_launch(void* const* d_in, const int* in_sizes, int n_in,
                              void* d_out, int out_size)
{
    const float* xpred   = (const float*)d_in[0];
    const float* Y       = (const float*)d_in[1];
    const float* lambdas = (const float*)d_in[2];
    const float* A       = (const float*)d_in[3];
    const float* B1      = (const float*)d_in[4];
    const float* B2      = (const float*)d_in[5];
    const float* C1      = (const float*)d_in[6];
    const float* D11     = (const float*)d_in[7];
    const float* D12     = (const float*)d_in[8];
    const float* C2      = (const float*)d_in[9];
    const float* D21     = (const float*)d_in[10];

    (void)in_sizes; (void)n_in;

    setup_kernel<<<1, 512>>>(Y, lambdas, A, B1, B2, C1, D11, D12, C2, D21);

    rnn_kernel<<<BB / 2, 512>>>(xpred);

    int write_xfinal = (out_size >= BB * TT * NY + BB * NX) ? 1 : 0;
    dim3 ygrid(BB, TT / 32);
    ypass_kernel<<<ygrid, 256>>>(xpred, (float*)d_out, write_xfinal);
}

// round 8
// speedup vs baseline: 1.5725x; 1.5457x over previous
#include <cuda_runtime.h>
#include <cstddef>

// Problem constants
#define NX 64
#define NU 32
#define NY 32
#define NW 64
#define BB 256
#define TT 2048

// Fused weight table gW[160][160] (row-major):
//  rows   0..63  (z):  [ C2*t_inv | D21*t_inv | (unused) ]
//  rows  64..127 (x):  [ Yinv^T A | Yinv^T B1 | Yinv^T B2]
//  rows 128..159 (y):  [ C1       | D11       | D12      ]
__device__ float gW[160 * 160];

// Per-thread packed weights gWT[s][96]:
//  s in [0,64)   : z row s, chunks 0..23 (96 floats)
//  s in [64,192) : idx=s-64: x row 64+(idx>>1), half h=idx&1, 20 chunks c=h+2i (80 floats)
//  s in [192,256): idx=s-192: y row 128+(idx>>1), half h, 20 chunks (80 floats)
__device__ float gWT[256 * 96];

// ---------------------------------------------------------------------------
// Setup: Newton-Schulz inverse of Y (X0=2I-Y; X <- X(2I - Y X), 4 iters),
// then fold Y_inv and t_inv into gW and pack gWT.
// ---------------------------------------------------------------------------
__global__ void __launch_bounds__(512, 1)
setup_kernel(const float* __restrict__ Y,
             const float* __restrict__ lambdas,
             const float* __restrict__ A,
             const float* __restrict__ B1,
             const float* __restrict__ B2,
             const float* __restrict__ C1,
             const float* __restrict__ D11,
             const float* __restrict__ D12,
             const float* __restrict__ C2,
             const float* __restrict__ D21)
{
    __shared__ float sX[64 * 64];
    __shared__ float sQ[64 * 64];
    __shared__ float sN[64 * 64];
    const int tid = threadIdx.x;   // 512 threads; each owns 8 elements

    // X0 = 2I - Y
    #pragma unroll
    for (int s = 0; s < 8; s++) {
        int e = tid + 512 * s;
        int i = e >> 6, j = e & 63;
        sX[e] = ((i == j) ? 2.0f : 0.0f) - Y[e];
    }
    __syncthreads();

    for (int it = 0; it < 4; it++) {
        // Q = 2I - Y @ X
        #pragma unroll
        for (int s = 0; s < 8; s++) {
            int e = tid + 512 * s;
            int i = e >> 6, j = e & 63;
            float acc = 0.0f;
            #pragma unroll 8
            for (int k = 0; k < 64; k++)
                acc += Y[i * 64 + k] * sX[k * 64 + j];
            sQ[e] = ((i == j) ? 2.0f : 0.0f) - acc;
        }
        __syncthreads();
        // N = X @ Q
        #pragma unroll
        for (int s = 0; s < 8; s++) {
            int e = tid + 512 * s;
            int i = e >> 6, j = e & 63;
            float acc = 0.0f;
            #pragma unroll 8
            for (int k = 0; k < 64; k++)
                acc += sX[i * 64 + k] * sQ[k * 64 + j];
            sN[e] = acc;
        }
        __syncthreads();
        #pragma unroll
        for (int s = 0; s < 8; s++) {
            int e = tid + 512 * s;
            sX[e] = sN[e];
        }
        __syncthreads();
    }
    // sX = Y^{-1}

    // --- build gW ---
    // z rows: [C2/lam | D21/lam]
    for (int e = tid; e < 64 * 64; e += 512) {
        int j = e >> 6, k2 = e & 63;
        gW[j * 160 + k2] = C2[j * 64 + k2] / lambdas[j];
    }
    for (int e = tid; e < 64 * 32; e += 512) {
        int j = e >> 5, m = e & 31;
        gW[j * 160 + 64 + m] = D21[j * 32 + m] / lambdas[j];
    }
    // x rows: Atil[j][k] = sum_i Yinv[i][j]*A[i][k]   (+B1til, B2til)
    for (int e = tid; e < 64 * 64; e += 512) {
        int j = e >> 6, k2 = e & 63;
        float sA = 0.0f, sB2 = 0.0f;
        #pragma unroll 8
        for (int i = 0; i < 64; i++) {
            float yi = sX[i * 64 + j];
            sA  += yi * A[i * 64 + k2];
            sB2 += yi * B2[i * 64 + k2];
        }
        gW[(64 + j) * 160 + k2]      = sA;
        gW[(64 + j) * 160 + 96 + k2] = sB2;
    }
    for (int e = tid; e < 64 * 32; e += 512) {
        int j = e >> 5, m = e & 31;
        float s = 0.0f;
        #pragma unroll 8
        for (int i = 0; i < 64; i++) s += sX[i * 64 + j] * B1[i * 32 + m];
        gW[(64 + j) * 160 + 64 + m] = s;
    }
    // y rows
    for (int e = tid; e < 32 * 64; e += 512) {
        int j = e >> 6, k2 = e & 63;
        gW[(128 + j) * 160 + k2]      = C1[j * 64 + k2];
        gW[(128 + j) * 160 + 96 + k2] = D12[j * 64 + k2];
    }
    for (int e = tid; e < 32 * 32; e += 512) {
        int j = e >> 5, m = e & 31;
        gW[(128 + j) * 160 + 64 + m] = D11[j * 32 + m];
    }
    __syncthreads();

    // --- pack gWT ---
    for (int s = tid; s < 256; s += 512) {
        if (s < 64) {
            for (int c = 0; c < 24; c++)
                #pragma unroll
                for (int j = 0; j < 4; j++)
                    gWT[s * 96 + 4 * c + j] = gW[s * 160 + 4 * c + j];
        } else {
            int row, h;
            if (s < 192) { int idx = s - 64;  row = 64 + (idx >> 1);  h = idx & 1; }
            else         { int idx = s - 192; row = 128 + (idx >> 1); h = idx & 1; }
            for (int i = 0; i < 20; i++) {
                int c = h + 2 * i;
                #pragma unroll
                for (int j = 0; j < 4; j++)
                    gWT[s * 96 + 4 * i + j] = gW[row * 160 + 4 * c + j];
            }
        }
    }
}

// ---------------------------------------------------------------------------
// helpers
// ---------------------------------------------------------------------------
__device__ __forceinline__ float2 u64_as_f2(unsigned long long x) {
    float2 r;
    asm("mov.b64 {%0, %1}, %2;" : "=f"(r.x), "=f"(r.y) : "l"(x));
    return r;
}
#define FFMA2(acc, w, vv) \
    asm("fma.rn.f32x2 %0, %1, %2, %0;" : "+l"(acc) : "l"(w), "l"(vv))
#define ADDF2(d, a, b) \
    asm("add.rn.f32x2 %0, %1, %2;" : "=l"(d) : "l"(a), "l"(b))
#define BARB(id) asm volatile("bar.sync %0, 256;" :: "r"(id) : "memory")

__device__ __forceinline__ float fast_tanh(float x) {
    // tanh(x) = 1 - 2/(exp(2x)+1), exp via ex2.approx
    float e;
    asm("ex2.approx.f32 %0, %1;" : "=f"(e) : "f"(x * 2.8853900817779268f));
    return 1.0f - __fdividef(2.0f, e + 1.0f);
}

// ---------------------------------------------------------------------------
// Main recurrent kernel: 128 CTAs x 512 threads, 2 batch chains per CTA.
// Warp->role map balanced across SMSPs (wid%4):
//   z warps: wid {0,1}(b0), {6,7}(b1)         (full 96-weight rows, 24 chunks)
//   x warps: wid {2,3,4,5}(b0), {10..13}(b1)  (half rows, 12+8 chunks)
//   y warps: wid {8,9}(b0), {14,15}(b1)       (half rows, 12+8 chunks)
// Every SMSP: 1 z + 2 x + 1 y warp. v=[x|u|w] in smem, broadcast reads.
// ---------------------------------------------------------------------------
__global__ void __launch_bounds__(512, 1)
rnn_kernel(const float* __restrict__ xpred, float* __restrict__ out, int write_xfinal)
{
    __shared__ __align__(16) float sv[2 * 160];

    const int tid  = threadIdx.x;
    const int wid  = tid >> 5;
    const int lane = tid & 31;

    const int isZ   = (0x00C3 >> wid) & 1;   // wid 0,1,6,7
    const int isY   = (0xC300 >> wid) & 1;   // wid 8,9,14,15
    const int batch = (0xFCC0 >> wid) & 1;   // wid 6,7,10..15
    const int widx  = isZ ? (wid & 1) : (isY ? (wid & 1) : ((wid - 2) & 3));

    float* v = sv + batch * 160;
    const int bg = blockIdx.x * 2 + batch;
    const float* uptr = xpred + (size_t)bg * TT * NU;
    float* yout = out + (size_t)bg * TT * NY;
    const int barid = batch + 1;

    if (isZ) {
        // ---------------- Z path: full row, 24 chunks (48 u64), 8 accs -----
        const int zr = widx * 32 + lane;           // z row 0..63
        const bool pref = (widx == 0);             // u-prefetch warp
        unsigned long long wreg[48];
        {
            const unsigned long long* grow = (const unsigned long long*)(gWT + zr * 96);
            #pragma unroll
            for (int i = 0; i < 48; i++) wreg[i] = grow[i];
        }

        // init: zero x region; load u0, prefetch u1
        v[zr] = 0.0f;
        float u_next = 0.0f;
        if (pref) {
            v[64 + lane] = uptr[lane];
            u_next = uptr[NU + lane];
        }
        BARB(barid);

        for (int t = 0; t < TT; t++) {
            unsigned long long a0=0ull,a1=0ull,a2=0ull,a3=0ull,a4=0ull,a5=0ull,a6=0ull,a7=0ull;
            #pragma unroll
            for (int c = 0; c < 24; c += 4) {
                ulonglong2 v0 = *(const ulonglong2*)(v + 4 * c);
                ulonglong2 v1 = *(const ulonglong2*)(v + 4 * c + 4);
                ulonglong2 v2 = *(const ulonglong2*)(v + 4 * c + 8);
                ulonglong2 v3 = *(const ulonglong2*)(v + 4 * c + 12);
                FFMA2(a0, wreg[2*c],   v0.x);
                FFMA2(a1, wreg[2*c+1], v0.y);
                FFMA2(a2, wreg[2*c+2], v1.x);
                FFMA2(a3, wreg[2*c+3], v1.y);
                FFMA2(a4, wreg[2*c+4], v2.x);
                FFMA2(a5, wreg[2*c+5], v2.y);
                FFMA2(a6, wreg[2*c+6], v3.x);
                FFMA2(a7, wreg[2*c+7], v3.y);
            }
            ADDF2(a0, a0, a4); ADDF2(a1, a1, a5);
            ADDF2(a2, a2, a6); ADDF2(a3, a3, a7);
            ADDF2(a0, a0, a2); ADDF2(a1, a1, a3);
            ADDF2(a0, a0, a1);
            float2 p = u64_as_f2(a0);
            v[96 + zr] = fast_tanh(p.x + p.y);   // publish w
            BARB(barid);                          // w visible

            if (pref) {
                v[64 + lane] = u_next;            // u_{t+1}
                if (t + 2 < TT) u_next = uptr[(size_t)(t + 2) * NU + lane];
            }
            BARB(barid);                          // x_next / u visible
        }

        if (write_xfinal) {
            out[(size_t)BB * TT * NY + (size_t)bg * NX + zr] = v[zr];
        }
    } else {
        // ---------------- X / Y path: half row, 12+8 chunks, 4 accumulators
        const int idx = widx * 32 + lane;          // 0..127 (x) / 0..63 (y)
        const int h   = idx & 1;
        const int j   = idx >> 1;                  // x: state row 0..63; y: out 0..31
        unsigned long long wreg[40];
        {
            const int s = (isY ? 192 : 64) + idx;
            const unsigned long long* grow = (const unsigned long long*)(gWT + s * 96);
            #pragma unroll
            for (int i = 0; i < 40; i++) wreg[i] = grow[i];
        }
        BARB(barid);

        const float* vh = v + 4 * h;   // chunk i at vh + 8*i

        for (int t = 0; t < TT; t++) {
            unsigned long long a0=0ull,a1=0ull,a2=0ull,a3=0ull;
            // Phase 1: 12 chunks of v[0:96]
            #pragma unroll
            for (int i = 0; i < 12; i += 2) {
                ulonglong2 v0 = *(const ulonglong2*)(vh + 8 * i);
                ulonglong2 v1 = *(const ulonglong2*)(vh + 8 * i + 8);
                FFMA2(a0, wreg[2*i],   v0.x);
                FFMA2(a1, wreg[2*i+1], v0.y);
                FFMA2(a2, wreg[2*i+2], v1.x);
                FFMA2(a3, wreg[2*i+3], v1.y);
            }
            BARB(barid);   // w visible

            // Phase 2: 8 chunks of v[96:160]
            #pragma unroll
            for (int i = 12; i < 20; i += 2) {
                ulonglong2 v0 = *(const ulonglong2*)(vh + 8 * i);
                ulonglong2 v1 = *(const ulonglong2*)(vh + 8 * i + 8);
                FFMA2(a0, wreg[2*i],   v0.x);
                FFMA2(a1, wreg[2*i+1], v0.y);
                FFMA2(a2, wreg[2*i+2], v1.x);
                FFMA2(a3, wreg[2*i+3], v1.y);
            }
            ADDF2(a0, a0, a2); ADDF2(a1, a1, a3); ADDF2(a0, a0, a1);
            float2 p = u64_as_f2(a0);
            float acc = p.x + p.y;
            acc += __shfl_xor_sync(0xffffffffu, acc, 1);   // combine halves
            if (h == 0) {
                if (!isY) v[j] = acc;                        // publish x_next
                else      yout[(size_t)t * NY + j] = acc;    // stream y
            }
            BARB(barid);   // x_next / u visible
        }
    }
}

// ---------------------------------------------------------------------------
extern "C" void kernel_launch(void* const* d_in, const int* in_sizes, int n_in,
                              void* d_out, int out_size)
{
    const float* xpred   = (const float*)d_in[0];
    const float* Y       = (const float*)d_in[1];
    const float* lambdas = (const float*)d_in[2];
    const float* A       = (const float*)d_in[3];
    const float* B1      = (const float*)d_in[4];
    const float* B2      = (const float*)d_in[5];
    const float* C1      = (const float*)d_in[6];
    const float* D11     = (const float*)d_in[7];
    const float* D12     = (const float*)d_in[8];
    const float* C2      = (const float*)d_in[9];
    const float* D21     = (const float*)d_in[10];

    (void)in_sizes; (void)n_in;

    setup_kernel<<<1, 512>>>(Y, lambdas, A, B1, B2, C1, D11, D12, C2, D21);

    int write_xfinal = (out_size >= BB * TT * NY + BB * NX) ? 1 : 0;
    rnn_kernel<<<BB / 2, 512>>>(xpred, (float*)d_out, write_xfinal);
}

// round 9
// speedup vs baseline: 1.5791x; 1.0042x over previous
#include <cuda_runtime.h>
#include <cstddef>

// Problem constants
#define NX 64
#define NU 32
#define NY 32
#define NW 64
#define BB 256
#define TT 2048

// Fused weight table gW[160][160] (row-major):
//  rows   0..63  (z):  [ C2*t_inv | D21*t_inv | (unused) ]
//  rows  64..127 (x):  [ Yinv^T A | Yinv^T B1 | Yinv^T B2]
//  rows 128..159 (y):  [ C1       | D11       | D12      ]
__device__ float gW[160 * 160];

// Per-thread packed weights gWT[s][96]:
//  s in [0,64)   : z row s, chunks 0..23 (96 floats)
//  s in [64,192) : idx=s-64: x row 64+(idx>>1), half h=idx&1, 20 chunks c=h+2i (80 floats)
//  s in [192,256): idx=s-192: y row 128+(idx>>1), half h, 20 chunks (80 floats)
__device__ float gWT[256 * 96];

// ---------------------------------------------------------------------------
// Setup: Newton-Schulz inverse of Y (X0=2I-Y; X <- X(2I - Y X), 4 iters),
// then fold Y_inv and t_inv into gW and pack gWT.
// ---------------------------------------------------------------------------
__global__ void __launch_bounds__(512, 1)
setup_kernel(const float* __restrict__ Y,
             const float* __restrict__ lambdas,
             const float* __restrict__ A,
             const float* __restrict__ B1,
             const float* __restrict__ B2,
             const float* __restrict__ C1,
             const float* __restrict__ D11,
             const float* __restrict__ D12,
             const float* __restrict__ C2,
             const float* __restrict__ D21)
{
    __shared__ float sX[64 * 64];
    __shared__ float sQ[64 * 64];
    __shared__ float sN[64 * 64];
    const int tid = threadIdx.x;   // 512 threads; each owns 8 elements

    // X0 = 2I - Y
    #pragma unroll
    for (int s = 0; s < 8; s++) {
        int e = tid + 512 * s;
        int i = e >> 6, j = e & 63;
        sX[e] = ((i == j) ? 2.0f : 0.0f) - Y[e];
    }
    __syncthreads();

    for (int it = 0; it < 4; it++) {
        // Q = 2I - Y @ X
        #pragma unroll
        for (int s = 0; s < 8; s++) {
            int e = tid + 512 * s;
            int i = e >> 6, j = e & 63;
            float acc = 0.0f;
            #pragma unroll 8
            for (int k = 0; k < 64; k++)
                acc += Y[i * 64 + k] * sX[k * 64 + j];
            sQ[e] = ((i == j) ? 2.0f : 0.0f) - acc;
        }
        __syncthreads();
        // N = X @ Q
        #pragma unroll
        for (int s = 0; s < 8; s++) {
            int e = tid + 512 * s;
            int i = e >> 6, j = e & 63;
            float acc = 0.0f;
            #pragma unroll 8
            for (int k = 0; k < 64; k++)
                acc += sX[i * 64 + k] * sQ[k * 64 + j];
            sN[e] = acc;
        }
        __syncthreads();
        #pragma unroll
        for (int s = 0; s < 8; s++) {
            int e = tid + 512 * s;
            sX[e] = sN[e];
        }
        __syncthreads();
    }
    // sX = Y^{-1}

    // --- build gW ---
    // z rows: [C2/lam | D21/lam]
    for (int e = tid; e < 64 * 64; e += 512) {
        int j = e >> 6, k2 = e & 63;
        gW[j * 160 + k2] = C2[j * 64 + k2] / lambdas[j];
    }
    for (int e = tid; e < 64 * 32; e += 512) {
        int j = e >> 5, m = e & 31;
        gW[j * 160 + 64 + m] = D21[j * 32 + m] / lambdas[j];
    }
    // x rows: Atil[j][k] = sum_i Yinv[i][j]*A[i][k]   (+B1til, B2til)
    for (int e = tid; e < 64 * 64; e += 512) {
        int j = e >> 6, k2 = e & 63;
        float sA = 0.0f, sB2 = 0.0f;
        #pragma unroll 8
        for (int i = 0; i < 64; i++) {
            float yi = sX[i * 64 + j];
            sA  += yi * A[i * 64 + k2];
            sB2 += yi * B2[i * 64 + k2];
        }
        gW[(64 + j) * 160 + k2]      = sA;
        gW[(64 + j) * 160 + 96 + k2] = sB2;
    }
    for (int e = tid; e < 64 * 32; e += 512) {
        int j = e >> 5, m = e & 31;
        float s = 0.0f;
        #pragma unroll 8
        for (int i = 0; i < 64; i++) s += sX[i * 64 + j] * B1[i * 32 + m];
        gW[(64 + j) * 160 + 64 + m] = s;
    }
    // y rows
    for (int e = tid; e < 32 * 64; e += 512) {
        int j = e >> 6, k2 = e & 63;
        gW[(128 + j) * 160 + k2]      = C1[j * 64 + k2];
        gW[(128 + j) * 160 + 96 + k2] = D12[j * 64 + k2];
    }
    for (int e = tid; e < 32 * 32; e += 512) {
        int j = e >> 5, m = e & 31;
        gW[(128 + j) * 160 + 64 + m] = D11[j * 32 + m];
    }
    __syncthreads();

    // --- pack gWT ---
    for (int s = tid; s < 256; s += 512) {
        if (s < 64) {
            for (int c = 0; c < 24; c++)
                #pragma unroll
                for (int j = 0; j < 4; j++)
                    gWT[s * 96 + 4 * c + j] = gW[s * 160 + 4 * c + j];
        } else {
            int row, h;
            if (s < 192) { int idx = s - 64;  row = 64 + (idx >> 1);  h = idx & 1; }
            else         { int idx = s - 192; row = 128 + (idx >> 1); h = idx & 1; }
            for (int i = 0; i < 20; i++) {
                int c = h + 2 * i;
                #pragma unroll
                for (int j = 0; j < 4; j++)
                    gWT[s * 96 + 4 * i + j] = gW[row * 160 + 4 * c + j];
            }
        }
    }
}

// ---------------------------------------------------------------------------
// helpers
// ---------------------------------------------------------------------------
__device__ __forceinline__ float2 u64_as_f2(unsigned long long x) {
    float2 r;
    asm("mov.b64 {%0, %1}, %2;" : "=f"(r.x), "=f"(r.y) : "l"(x));
    return r;
}
#define FFMA2(acc, w, vv) \
    asm("fma.rn.f32x2 %0, %1, %2, %0;" : "+l"(acc) : "l"(w), "l"(vv))
#define ADDF2(d, a, b) \
    asm("add.rn.f32x2 %0, %1, %2;" : "=l"(d) : "l"(a), "l"(b))
#define BARB(id) asm volatile("bar.sync %0, 256;" :: "r"(id) : "memory")

__device__ __forceinline__ float fast_tanh(float x) {
    // tanh(x) = 1 - 2/(exp(2x)+1), exp via ex2.approx
    float e;
    asm("ex2.approx.f32 %0, %1;" : "=f"(e) : "f"(x * 2.8853900817779268f));
    return 1.0f - __fdividef(2.0f, e + 1.0f);
}

// ---------------------------------------------------------------------------
// Main recurrent kernel: 128 CTAs x 512 threads, 2 batch chains per CTA.
// Warp->role map (batch = wid&1; SMSP = wid&3):
//   y: wid 0..3   (lowest arbiter priority — never on critical path)
//   x: wid 4..11
//   z: wid 12..15 (HIGHEST priority — z is the bar1 critical producer)
// Every SMSP hosts exactly 1z + 2x + 1y. Batch-1 group is phase-staggered
// ~320 cyc so the two chains' barrier-stall windows anti-align.
// ---------------------------------------------------------------------------
__global__ void __launch_bounds__(512, 1)
rnn_kernel(const float* __restrict__ xpred, float* __restrict__ out, int write_xfinal)
{
    __shared__ __align__(16) float sv[2 * 160];

    const int tid  = threadIdx.x;
    const int wid  = tid >> 5;
    const int lane = tid & 31;

    const int isZ   = (wid >= 12);
    const int isY   = (wid < 4);
    const int batch = wid & 1;
    const int widx  = isZ ? ((wid - 12) >> 1) : (isY ? (wid >> 1) : ((wid - 4) >> 1));

    float* v = sv + batch * 160;
    const int bg = blockIdx.x * 2 + batch;
    const float* uptr = xpred + (size_t)bg * TT * NU;
    float* yout = out + (size_t)bg * TT * NY;
    const int barid = batch + 1;

    // Anti-phase stagger for batch 1: ~320 cyc dependent-FMA delay before the
    // group's first barrier. Deterministic; result never used (cond is false).
    if (batch == 1) {
        float d = 1.0f;
        #pragma unroll 1
        for (int i = 0; i < 80; i++) d = __fmaf_rn(d, 0.9999999f, 1e-7f);
        if (d < 0.0f) sv[0] = d;   // unreachable: chain stays positive
    }

    if (isZ) {
        // ---------------- Z path: full row, 24 chunks (48 u64), 8 accs -----
        const int zr = widx * 32 + lane;           // z row 0..63
        const bool pref = (widx == 0);             // u-prefetch warp
        unsigned long long wreg[48];
        {
            const unsigned long long* grow = (const unsigned long long*)(gWT + zr * 96);
            #pragma unroll
            for (int i = 0; i < 48; i++) wreg[i] = grow[i];
        }

        // init: zero x region; load u0, prefetch u1
        v[zr] = 0.0f;
        float u_next = 0.0f;
        if (pref) {
            v[64 + lane] = uptr[lane];
            u_next = uptr[NU + lane];
        }
        BARB(barid);

        for (int t = 0; t < TT; t++) {
            unsigned long long a0=0ull,a1=0ull,a2=0ull,a3=0ull,a4=0ull,a5=0ull,a6=0ull,a7=0ull;
            #pragma unroll
            for (int c = 0; c < 24; c += 4) {
                ulonglong2 v0 = *(const ulonglong2*)(v + 4 * c);
                ulonglong2 v1 = *(const ulonglong2*)(v + 4 * c + 4);
                ulonglong2 v2 = *(const ulonglong2*)(v + 4 * c + 8);
                ulonglong2 v3 = *(const ulonglong2*)(v + 4 * c + 12);
                FFMA2(a0, wreg[2*c],   v0.x);
                FFMA2(a1, wreg[2*c+1], v0.y);
                FFMA2(a2, wreg[2*c+2], v1.x);
                FFMA2(a3, wreg[2*c+3], v1.y);
                FFMA2(a4, wreg[2*c+4], v2.x);
                FFMA2(a5, wreg[2*c+5], v2.y);
                FFMA2(a6, wreg[2*c+6], v3.x);
                FFMA2(a7, wreg[2*c+7], v3.y);
            }
            ADDF2(a0, a0, a4); ADDF2(a1, a1, a5);
            ADDF2(a2, a2, a6); ADDF2(a3, a3, a7);
            ADDF2(a0, a0, a2); ADDF2(a1, a1, a3);
            ADDF2(a0, a0, a1);
            float2 p = u64_as_f2(a0);
            v[96 + zr] = fast_tanh(p.x + p.y);   // publish w
            BARB(barid);                          // w visible

            if (pref) {
                v[64 + lane] = u_next;            // u_{t+1}
                if (t + 2 < TT) u_next = uptr[(size_t)(t + 2) * NU + lane];
            }
            BARB(barid);                          // x_next / u visible
        }

        if (write_xfinal) {
            out[(size_t)BB * TT * NY + (size_t)bg * NX + zr] = v[zr];
        }
    } else {
        // ---------------- X / Y path: half row, 12+8 chunks, 4 accumulators
        const int idx = widx * 32 + lane;          // 0..127 (x) / 0..63 (y)
        const int h   = idx & 1;
        const int j   = idx >> 1;                  // x: state row 0..63; y: out 0..31
        unsigned long long wreg[40];
        {
            const int s = (isY ? 192 : 64) + idx;
            const unsigned long long* grow = (const unsigned long long*)(gWT + s * 96);
            #pragma unroll
            for (int i = 0; i < 40; i++) wreg[i] = grow[i];
        }
        BARB(barid);

        const float* vh = v + 4 * h;   // chunk i at vh + 8*i

        for (int t = 0; t < TT; t++) {
            unsigned long long a0=0ull,a1=0ull,a2=0ull,a3=0ull;
            // Phase 1: 12 chunks of v[0:96]
            #pragma unroll
            for (int i = 0; i < 12; i += 2) {
                ulonglong2 v0 = *(const ulonglong2*)(vh + 8 * i);
                ulonglong2 v1 = *(const ulonglong2*)(vh + 8 * i + 8);
                FFMA2(a0, wreg[2*i],   v0.x);
                FFMA2(a1, wreg[2*i+1], v0.y);
                FFMA2(a2, wreg[2*i+2], v1.x);
                FFMA2(a3, wreg[2*i+3], v1.y);
            }
            BARB(barid);   // w visible

            // Phase 2: 8 chunks of v[96:160]
            #pragma unroll
            for (int i = 12; i < 20; i += 2) {
                ulonglong2 v0 = *(const ulonglong2*)(vh + 8 * i);
                ulonglong2 v1 = *(const ulonglong2*)(vh + 8 * i + 8);
                FFMA2(a0, wreg[2*i],   v0.x);
                FFMA2(a1, wreg[2*i+1], v0.y);
                FFMA2(a2, wreg[2*i+2], v1.x);
                FFMA2(a3, wreg[2*i+3], v1.y);
            }
            ADDF2(a0, a0, a2); ADDF2(a1, a1, a3); ADDF2(a0, a0, a1);
            float2 p = u64_as_f2(a0);
            float acc = p.x + p.y;
            acc += __shfl_xor_sync(0xffffffffu, acc, 1);   // combine halves
            if (h == 0) {
                if (!isY) v[j] = acc;                        // publish x_next
                else      yout[(size_t)t * NY + j] = acc;    // stream y
            }
            BARB(barid);   // x_next / u visible
        }
    }
}

// ---------------------------------------------------------------------------
extern "C" void kernel_launch(void* const* d_in, const int* in_sizes, int n_in,
                              void* d_out, int out_size)
{
    const float* xpred   = (const float*)d_in[0];
    const float* Y       = (const float*)d_in[1];
    const float* lambdas = (const float*)d_in[2];
    const float* A       = (const float*)d_in[3];
    const float* B1      = (const float*)d_in[4];
    const float* B2      = (const float*)d_in[5];
    const float* C1      = (const float*)d_in[6];
    const float* D11     = (const float*)d_in[7];
    const float* D12     = (const float*)d_in[8];
    const float* C2      = (const float*)d_in[9];
    const float* D21     = (const float*)d_in[10];

    (void)in_sizes; (void)n_in;

    setup_kernel<<<1, 512>>>(Y, lambdas, A, B1, B2, C1, D11, D12, C2, D21);

    int write_xfinal = (out_size >= BB * TT * NY + BB * NX) ? 1 : 0;
    rnn_kernel<<<BB / 2, 512>>>(xpred, (float*)d_out, write_xfinal);
}

// round 10
// speedup vs baseline: 1.9353x; 1.2256x over previous
#include <cuda_runtime.h>
#include <cstddef>

// Problem constants
#define NX 64
#define NU 32
#define NY 32
#define NW 64
#define BB 256
#define TT 2048

// Fused weight table gW[160][160] (row-major):
//  rows   0..63  (z):  [ C2*t_inv | D21*t_inv | (unused) ]
//  rows  64..127 (x):  [ Yinv^T A | Yinv^T B1 | Yinv^T B2]
//  rows 128..159 (y):  [ C1       | D11       | D12      ]
__device__ float gW[160 * 160];

// Per-thread packed weights gWT[s][96]:
//  s in [0,64)   : z row s, chunks 0..23 (96 floats)
//  s in [64,192) : idx=s-64: x row 64+(idx>>1), half h=idx&1, 20 chunks c=h+2i (80 floats)
//  s in [192,256): idx=s-192: y row 128+(idx>>1), half h, 20 chunks (80 floats)
// Chunk sections (cols): x-part c0..15 (i0..7 for halves), u-part c16..23
// (i8..11), w-part c24..39 (i12..19).
__device__ float gWT[256 * 96];

// ---------------------------------------------------------------------------
// Setup: Newton-Schulz inverse of Y, fold Y_inv and t_inv into gW, pack gWT.
// ---------------------------------------------------------------------------
__global__ void __launch_bounds__(512, 1)
setup_kernel(const float* __restrict__ Y,
             const float* __restrict__ lambdas,
             const float* __restrict__ A,
             const float* __restrict__ B1,
             const float* __restrict__ B2,
             const float* __restrict__ C1,
             const float* __restrict__ D11,
             const float* __restrict__ D12,
             const float* __restrict__ C2,
             const float* __restrict__ D21)
{
    __shared__ float sX[64 * 64];
    __shared__ float sQ[64 * 64];
    __shared__ float sN[64 * 64];
    const int tid = threadIdx.x;   // 512 threads

    #pragma unroll
    for (int s = 0; s < 8; s++) {
        int e = tid + 512 * s;
        int i = e >> 6, j = e & 63;
        sX[e] = ((i == j) ? 2.0f : 0.0f) - Y[e];
    }
    __syncthreads();

    for (int it = 0; it < 4; it++) {
        #pragma unroll
        for (int s = 0; s < 8; s++) {
            int e = tid + 512 * s;
            int i = e >> 6, j = e & 63;
            float acc = 0.0f;
            #pragma unroll 8
            for (int k = 0; k < 64; k++)
                acc += Y[i * 64 + k] * sX[k * 64 + j];
            sQ[e] = ((i == j) ? 2.0f : 0.0f) - acc;
        }
        __syncthreads();
        #pragma unroll
        for (int s = 0; s < 8; s++) {
            int e = tid + 512 * s;
            int i = e >> 6, j = e & 63;
            float acc = 0.0f;
            #pragma unroll 8
            for (int k = 0; k < 64; k++)
                acc += sX[i * 64 + k] * sQ[k * 64 + j];
            sN[e] = acc;
        }
        __syncthreads();
        #pragma unroll
        for (int s = 0; s < 8; s++) {
            int e = tid + 512 * s;
            sX[e] = sN[e];
        }
        __syncthreads();
    }
    // sX = Y^{-1}

    for (int e = tid; e < 64 * 64; e += 512) {
        int j = e >> 6, k2 = e & 63;
        gW[j * 160 + k2] = C2[j * 64 + k2] / lambdas[j];
    }
    for (int e = tid; e < 64 * 32; e += 512) {
        int j = e >> 5, m = e & 31;
        gW[j * 160 + 64 + m] = D21[j * 32 + m] / lambdas[j];
    }
    for (int e = tid; e < 64 * 64; e += 512) {
        int j = e >> 6, k2 = e & 63;
        float sA = 0.0f, sB2 = 0.0f;
        #pragma unroll 8
        for (int i = 0; i < 64; i++) {
            float yi = sX[i * 64 + j];
            sA  += yi * A[i * 64 + k2];
            sB2 += yi * B2[i * 64 + k2];
        }
        gW[(64 + j) * 160 + k2]      = sA;
        gW[(64 + j) * 160 + 96 + k2] = sB2;
    }
    for (int e = tid; e < 64 * 32; e += 512) {
        int j = e >> 5, m = e & 31;
        float s = 0.0f;
        #pragma unroll 8
        for (int i = 0; i < 64; i++) s += sX[i * 64 + j] * B1[i * 32 + m];
        gW[(64 + j) * 160 + 64 + m] = s;
    }
    for (int e = tid; e < 32 * 64; e += 512) {
        int j = e >> 6, k2 = e & 63;
        gW[(128 + j) * 160 + k2]      = C1[j * 64 + k2];
        gW[(128 + j) * 160 + 96 + k2] = D12[j * 64 + k2];
    }
    for (int e = tid; e < 32 * 32; e += 512) {
        int j = e >> 5, m = e & 31;
        gW[(128 + j) * 160 + 64 + m] = D11[j * 32 + m];
    }
    __syncthreads();

    for (int s = tid; s < 256; s += 512) {
        if (s < 64) {
            for (int c = 0; c < 24; c++)
                #pragma unroll
                for (int j = 0; j < 4; j++)
                    gWT[s * 96 + 4 * c + j] = gW[s * 160 + 4 * c + j];
        } else {
            int row, h;
            if (s < 192) { int idx = s - 64;  row = 64 + (idx >> 1);  h = idx & 1; }
            else         { int idx = s - 192; row = 128 + (idx >> 1); h = idx & 1; }
            for (int i = 0; i < 20; i++) {
                int c = h + 2 * i;
                #pragma unroll
                for (int j = 0; j < 4; j++)
                    gWT[s * 96 + 4 * i + j] = gW[row * 160 + 4 * c + j];
            }
        }
    }
}

// ---------------------------------------------------------------------------
// helpers
// ---------------------------------------------------------------------------
__device__ __forceinline__ float2 u64_as_f2(unsigned long long x) {
    float2 r;
    asm("mov.b64 {%0, %1}, %2;" : "=f"(r.x), "=f"(r.y) : "l"(x));
    return r;
}
#define FFMA2(acc, w, vv) \
    asm("fma.rn.f32x2 %0, %1, %2, %0;" : "+l"(acc) : "l"(w), "l"(vv))
#define ADDF2(d, a, b) \
    asm("add.rn.f32x2 %0, %1, %2;" : "=l"(d) : "l"(a), "l"(b))
#define BARB(id) asm volatile("bar.sync %0, 256;" :: "r"(id) : "memory")

__device__ __forceinline__ float fast_tanh(float x) {
    float e;
    asm("ex2.approx.f32 %0, %1;" : "=f"(e) : "f"(x * 2.8853900817779268f));
    return 1.0f - __fdividef(2.0f, e + 1.0f);
}

// ---------------------------------------------------------------------------
// Main recurrent kernel: 128 CTAs x 512 threads, 2 batch chains per CTA.
// Software-pipelined: u-partials for step t+1 are computed in phase B of
// step t (u is input data, known early). Critical chain per step:
//   barB -> z: 16 x-chunks + tanh -> barA -> x/y: 8 w-chunks + shfl -> barB
// smem per batch: vx[64] | vw[64] | vu[2][32] (u double-buffered).
// Warp->role (batch = wid&1): y wid0..3 (widx0 = u-stager), x wid4..11,
// z wid12..15 (highest arbiter priority).
// ---------------------------------------------------------------------------
__global__ void __launch_bounds__(512, 1)
rnn_kernel(const float* __restrict__ xpred, float* __restrict__ out, int write_xfinal)
{
    __shared__ __align__(16) float sv[2 * 192];

    const int tid  = threadIdx.x;
    const int wid  = tid >> 5;
    const int lane = tid & 31;

    const int isZ   = (wid >= 12);
    const int isY   = (wid < 4);
    const int batch = wid & 1;
    const int widx  = isZ ? ((wid - 12) >> 1) : (isY ? (wid >> 1) : ((wid - 4) >> 1));

    float* vx = sv + batch * 192;        // x_t      [64]
    float* vw = vx + 64;                  // w_t      [64]
    float* vu = vx + 128;                 // u bufs   [2][32]
    const int bg = blockIdx.x * 2 + batch;
    const float* uptr = xpred + (size_t)bg * TT * NU;
    float* yout = out + (size_t)bg * TT * NY;
    const int barid = batch + 1;

    if (isZ) {
        // ================= Z path: full row ===============================
        const int zr = widx * 32 + lane;     // z row 0..63
        unsigned long long wreg[48];
        {
            const unsigned long long* grow = (const unsigned long long*)(gWT + zr * 96);
            #pragma unroll
            for (int i = 0; i < 48; i++) wreg[i] = grow[i];
        }

        vx[zr] = 0.0f;                       // x0 = 0
        BARB(barid);                         // u_0 staged by y-warp

        // prologue: u-partial for t=0 from vu buf0
        unsigned long long u0 = 0ull, u1 = 0ull;
        {
            const float* ub = vu;            // buf 0
            #pragma unroll
            for (int c = 0; c < 8; c += 2) {
                ulonglong2 q0 = *(const ulonglong2*)(ub + 4 * c);
                ulonglong2 q1 = *(const ulonglong2*)(ub + 4 * c + 4);
                FFMA2(u0, wreg[32 + 2*c],     q0.x);
                FFMA2(u1, wreg[32 + 2*c + 1], q0.y);
                FFMA2(u0, wreg[32 + 2*c + 2], q1.x);
                FFMA2(u1, wreg[32 + 2*c + 3], q1.y);
            }
            ADDF2(u0, u0, u1);
        }

        for (int t = 0; t < TT; t++) {
            // ---- Phase A: x-part (16 chunks) + combine + tanh ----
            unsigned long long a0=0ull,a1=0ull,a2=0ull,a3=0ull;
            #pragma unroll
            for (int c = 0; c < 16; c += 2) {
                ulonglong2 v0 = *(const ulonglong2*)(vx + 4 * c);
                ulonglong2 v1 = *(const ulonglong2*)(vx + 4 * c + 4);
                FFMA2(a0, wreg[2*c],   v0.x);
                FFMA2(a1, wreg[2*c+1], v0.y);
                FFMA2(a2, wreg[2*c+2], v1.x);
                FFMA2(a3, wreg[2*c+3], v1.y);
            }
            ADDF2(a0, a0, a2); ADDF2(a1, a1, a3);
            ADDF2(a0, a0, a1); ADDF2(a0, a0, u0);
            float2 p = u64_as_f2(a0);
            vw[zr] = fast_tanh(p.x + p.y);   // publish w_t
            BARB(barid);                      // barA

            // ---- Phase B: u-partial for t+1 (8 chunks from buf (t+1)&1) ----
            const float* ub = vu + ((t + 1) & 1) * 32;
            unsigned long long b0=0ull,b1=0ull,b2=0ull,b3=0ull;
            #pragma unroll
            for (int c = 0; c < 8; c += 2) {
                ulonglong2 q0 = *(const ulonglong2*)(ub + 4 * c);
                ulonglong2 q1 = *(const ulonglong2*)(ub + 4 * c + 4);
                FFMA2(b0, wreg[32 + 2*c],     q0.x);
                FFMA2(b1, wreg[32 + 2*c + 1], q0.y);
                FFMA2(b2, wreg[32 + 2*c + 2], q1.x);
                FFMA2(b3, wreg[32 + 2*c + 3], q1.y);
            }
            ADDF2(b0, b0, b2); ADDF2(b1, b1, b3); ADDF2(u0, b0, b1);
            BARB(barid);                      // barB: x_{t+1}, u staged
        }

        if (write_xfinal) {
            out[(size_t)BB * TT * NY + (size_t)bg * NX + zr] = vx[zr];
        }
    } else {
        // ================= X / Y path: half rows ==========================
        const int idx = widx * 32 + lane;     // 0..127 (x) / 0..63 (y)
        const int h   = idx & 1;
        const int j   = idx >> 1;             // x: state row; y: output col
        const bool stager = (isY && widx == 0);   // u staging lanes
        unsigned long long wreg[40];
        {
            const int s = (isY ? 192 : 64) + idx;
            const unsigned long long* grow = (const unsigned long long*)(gWT + s * 96);
            #pragma unroll
            for (int i = 0; i < 40; i++) wreg[i] = grow[i];
        }

        // stage u_0 into buf0; u_next = u_1
        float u_next = 0.0f;
        if (stager) {
            vu[lane] = uptr[lane];
            u_next = uptr[NU + lane];
        }
        BARB(barid);

        const float* vxh = vx + 4 * h;
        const float* vwh = vw + 4 * h;

        // prologue: u-partial for t=0 (4 chunks, weights i=8..11)
        unsigned long long u0 = 0ull, u1 = 0ull;
        {
            const float* ub = vu + 4 * h;     // buf 0
            #pragma unroll
            for (int i = 8; i < 12; i += 2) {
                ulonglong2 q0 = *(const ulonglong2*)(ub + 8 * (i - 8));
                ulonglong2 q1 = *(const ulonglong2*)(ub + 8 * (i - 8) + 8);
                FFMA2(u0, wreg[2*i],   q0.x);
                FFMA2(u1, wreg[2*i+1], q0.y);
                FFMA2(u0, wreg[2*i+2], q1.x);
                FFMA2(u1, wreg[2*i+3], q1.y);
            }
            ADDF2(u0, u0, u1);
        }

        for (int t = 0; t < TT; t++) {
            // ---- Phase A: x-part (8 chunks, i=0..7); stager refreshes u ----
            unsigned long long a0=0ull,a1=0ull,a2=0ull,a3=0ull;
            #pragma unroll
            for (int i = 0; i < 8; i += 2) {
                ulonglong2 v0 = *(const ulonglong2*)(vxh + 8 * i);
                ulonglong2 v1 = *(const ulonglong2*)(vxh + 8 * i + 8);
                FFMA2(a0, wreg[2*i],   v0.x);
                FFMA2(a1, wreg[2*i+1], v0.y);
                FFMA2(a2, wreg[2*i+2], v1.x);
                FFMA2(a3, wreg[2*i+3], v1.y);
            }
            if (stager) {
                vu[((t + 1) & 1) * 32 + lane] = u_next;   // u_{t+1}
                if (t + 2 < TT) u_next = uptr[(size_t)(t + 2) * NU + lane];
            }
            BARB(barid);   // barA: w_t visible

            // ---- Phase B: w-part (8 chunks, i=12..19) + publish ----
            #pragma unroll
            for (int i = 12; i < 20; i += 2) {
                ulonglong2 v0 = *(const ulonglong2*)(vwh + 8 * (i - 12));
                ulonglong2 v1 = *(const ulonglong2*)(vwh + 8 * (i - 12) + 8);
                FFMA2(a0, wreg[2*i],   v0.x);
                FFMA2(a1, wreg[2*i+1], v0.y);
                FFMA2(a2, wreg[2*i+2], v1.x);
                FFMA2(a3, wreg[2*i+3], v1.y);
            }
            ADDF2(a0, a0, a2); ADDF2(a1, a1, a3);
            ADDF2(a0, a0, a1); ADDF2(a0, a0, u0);
            float2 p = u64_as_f2(a0);
            float acc = p.x + p.y;
            acc += __shfl_xor_sync(0xffffffffu, acc, 1);   // combine halves
            if (h == 0) {
                if (!isY) vx[j] = acc;                       // publish x_{t+1}
                else      yout[(size_t)t * NY + j] = acc;    // stream y_t
            }

            // u-partial for t+1 (4 chunks, buf (t+1)&1) — off critical path
            {
                const float* ub = vu + ((t + 1) & 1) * 32 + 4 * h;
                unsigned long long b0 = 0ull, b1 = 0ull;
                #pragma unroll
                for (int i = 8; i < 12; i += 2) {
                    ulonglong2 q0 = *(const ulonglong2*)(ub + 8 * (i - 8));
                    ulonglong2 q1 = *(const ulonglong2*)(ub + 8 * (i - 8) + 8);
                    FFMA2(b0, wreg[2*i],   q0.x);
                    FFMA2(b1, wreg[2*i+1], q0.y);
                    FFMA2(b0, wreg[2*i+2], q1.x);
                    FFMA2(b1, wreg[2*i+3], q1.y);
                }
                ADDF2(u0, b0, b1);
            }
            BARB(barid);   // barB: x_{t+1}, u staged
        }
    }
}

// ---------------------------------------------------------------------------
extern "C" void kernel_launch(void* const* d_in, const int* in_sizes, int n_in,
                              void* d_out, int out_size)
{
    const float* xpred   = (const float*)d_in[0];
    const float* Y       = (const float*)d_in[1];
    const float* lambdas = (const float*)d_in[2];
    const float* A       = (const float*)d_in[3];
    const float* B1      = (const float*)d_in[4];
    const float* B2      = (const float*)d_in[5];
    const float* C1      = (const float*)d_in[6];
    const float* D11     = (const float*)d_in[7];
    const float* D12     = (const float*)d_in[8];
    const float* C2      = (const float*)d_in[9];
    const float* D21     = (const float*)d_in[10];

    (void)in_sizes; (void)n_in;

    setup_kernel<<<1, 512>>>(Y, lambdas, A, B1, B2, C1, D11, D12, C2, D21);

    int write_xfinal = (out_size >= BB * TT * NY + BB * NX) ? 1 : 0;
    rnn_kernel<<<BB / 2, 512>>>(xpred, (float*)d_out, write_xfinal);
}